// round 1
// baseline (speedup 1.0000x reference)
#include <cuda_runtime.h>
#include <cuda_bf16.h>

// Problem constants
#define NB   4
#define C    256
#define CQK  32
#define HW   4096
#define BM   64
#define BN   64

// Scratch: projected tensors, transposed to [s][ch] for coalesced tile loads.
// qkT[n][s][0..31]=q, [32..63]=k ; vT[n][s][0..255]=v
__device__ float g_qkT[NB * HW * 64];
__device__ float g_vT [NB * HW * C];

// ---------------------------------------------------------------------------
// Kernel 1: fused projections.  Per batch: O[320,4096] = W[320,256] @ X[256,4096] + b
// rows 0..31 = Wq, 32..63 = Wk, 64..319 = Wv.
// grid = (5 out-tiles of 64, 64 s-tiles of 64, 4 batches), block = 256
// ---------------------------------------------------------------------------
__global__ __launch_bounds__(256) void proj_kernel(
    const float* __restrict__ x,
    const float* __restrict__ Wq, const float* __restrict__ bq,
    const float* __restrict__ Wk, const float* __restrict__ bk,
    const float* __restrict__ Wv, const float* __restrict__ bv)
{
    const int ot = blockIdx.x;          // 0..4 (out-row tile)
    const int st = blockIdx.y;          // 0..63 (spatial tile)
    const int n  = blockIdx.z;
    const int s0 = st * 64;
    const int r0g = ot * 64;

    __shared__ float Ws[32][68];        // [k][r]  (transposed for contiguous r)
    __shared__ float Xs[32][68];        // [k][s]

    const int tid = threadIdx.x;
    const int tx = tid & 15;            // -> r block
    const int ty = tid >> 4;            // -> s block

    float o[4][4];                      // o[ss][rr]
    #pragma unroll
    for (int a = 0; a < 4; a++)
        #pragma unroll
        for (int b = 0; b < 4; b++) o[a][b] = 0.f;

    const float* xb = x + (size_t)n * C * HW;

    for (int k0 = 0; k0 < 256; k0 += 32) {
        // load W chunk (rows r0g..r0g+63, cols k0..k0+31) transposed
        for (int idx = tid; idx < 64 * 32; idx += 256) {
            int r = idx >> 5, c = idx & 31;
            int R = r0g + r;
            float w;
            if (R < 32)       w = Wq[R * 256 + k0 + c];
            else if (R < 64)  w = Wk[(R - 32) * 256 + k0 + c];
            else              w = Wv[(R - 64) * 256 + k0 + c];
            Ws[c][r] = w;
        }
        // load X chunk [32 k][64 s]
        for (int idx = tid; idx < 32 * 64; idx += 256) {
            int c = idx >> 6, s = idx & 63;
            Xs[c][s] = xb[(size_t)(k0 + c) * HW + s0 + s];
        }
        __syncthreads();
        #pragma unroll 8
        for (int c = 0; c < 32; c++) {
            float4 a = *(const float4*)&Ws[c][tx * 4];
            float4 b = *(const float4*)&Xs[c][ty * 4];
            o[0][0] += b.x * a.x; o[0][1] += b.x * a.y; o[0][2] += b.x * a.z; o[0][3] += b.x * a.w;
            o[1][0] += b.y * a.x; o[1][1] += b.y * a.y; o[1][2] += b.y * a.z; o[1][3] += b.y * a.w;
            o[2][0] += b.z * a.x; o[2][1] += b.z * a.y; o[2][2] += b.z * a.z; o[2][3] += b.z * a.w;
            o[3][0] += b.w * a.x; o[3][1] += b.w * a.y; o[3][2] += b.w * a.z; o[3][3] += b.w * a.w;
        }
        __syncthreads();
    }

    // bias per output row
    float bias[4];
    #pragma unroll
    for (int rr = 0; rr < 4; rr++) {
        int R = r0g + tx * 4 + rr;
        if (R < 32)      bias[rr] = bq[R];
        else if (R < 64) bias[rr] = bk[R - 32];
        else             bias[rr] = bv[R - 64];
    }

    // write transposed: [s][r]
    #pragma unroll
    for (int ss = 0; ss < 4; ss++) {
        int s = s0 + ty * 4 + ss;
        float4 v = make_float4(o[ss][0] + bias[0], o[ss][1] + bias[1],
                               o[ss][2] + bias[2], o[ss][3] + bias[3]);
        if (ot == 0) {
            *(float4*)&g_qkT[((size_t)n * HW + s) * 64 + tx * 4] = v;
        } else {
            *(float4*)&g_vT[((size_t)n * HW + s) * C + (ot - 1) * 64 + tx * 4] = v;
        }
    }
}

// ---------------------------------------------------------------------------
// Kernel 2: flash attention.  grid = (64 q-tiles, 4 batches), block = 256.
// Per CTA: Q tile [64,32]; loop over 64 KV tiles: S=QK^T, online softmax,
// O[64,256] += P @ V.  Dynamic smem ~103KB -> 2 CTAs/SM.
// ---------------------------------------------------------------------------
#define SM_QS   0
#define SM_KS   (32 * 68)
#define SM_PT   (2 * 32 * 68)
#define SM_VS   (SM_PT + 64 * 68)
#define SM_M    (SM_VS + 64 * 264)
#define SM_L    (SM_M + 64)
#define SM_CR   (SM_L + 64)
#define SM_TOT  (SM_CR + 64)

__global__ __launch_bounds__(256, 2) void flash_kernel(float* __restrict__ out)
{
    extern __shared__ float sm[];
    float* Qs  = sm + SM_QS;    // [kk][i]   stride 68
    float* Ks  = sm + SM_KS;    // [kk][j]   stride 68
    float* Pt  = sm + SM_PT;    // [j][i]    stride 68
    float* Vs  = sm + SM_VS;    // [j][c]    stride 264
    float* mrow = sm + SM_M;
    float* lrow = sm + SM_L;
    float* crow = sm + SM_CR;

    const int qt = blockIdx.x;
    const int n  = blockIdx.y;
    const int i0g = qt * 64;
    const int tid = threadIdx.x;
    const int tx = tid & 15;    // -> query rows i0 = tx*4
    const int ty = tid >> 4;    // -> channel block c0 = ty*16

    const float* qkT = g_qkT + (size_t)n * HW * 64;
    const float* vT  = g_vT  + (size_t)n * HW * C;

    // load Q tile transposed: Qs[kk][i]
    for (int idx = tid; idx < 64 * 32; idx += 256) {
        int i = idx >> 5, kk = idx & 31;
        Qs[kk * 68 + i] = qkT[(size_t)(i0g + i) * 64 + kk];
    }
    if (tid < 64) { mrow[tid] = -1e30f; lrow[tid] = 0.f; }

    float o[4][16];
    #pragma unroll
    for (int r = 0; r < 4; r++)
        #pragma unroll
        for (int c = 0; c < 16; c++) o[r][c] = 0.f;

    __syncthreads();

    for (int jt = 0; jt < 64; jt++) {
        const int j0g = jt * 64;
        // load K tile transposed: Ks[kk][j]
        for (int idx = tid; idx < 64 * 32; idx += 256) {
            int j = idx >> 5, kk = idx & 31;
            Ks[kk * 68 + j] = qkT[(size_t)(j0g + j) * 64 + 32 + kk];
        }
        // load V tile: Vs[j][c] (float4)
        for (int idx = tid; idx < 64 * 64; idx += 256) {
            int j = idx >> 6, c4 = idx & 63;
            *(float4*)&Vs[j * 264 + c4 * 4] = *(const float4*)&vT[(size_t)(j0g + j) * C + c4 * 4];
        }
        __syncthreads();

        // S[i][j] = sum_kk Q[i][kk] K[j][kk]
        float s[4][4];
        #pragma unroll
        for (int a = 0; a < 4; a++)
            #pragma unroll
            for (int b = 0; b < 4; b++) s[a][b] = 0.f;
        #pragma unroll 8
        for (int kk = 0; kk < 32; kk++) {
            float4 a = *(const float4*)&Qs[kk * 68 + tx * 4];
            float4 b = *(const float4*)&Ks[kk * 68 + ty * 4];
            s[0][0] += a.x * b.x; s[0][1] += a.x * b.y; s[0][2] += a.x * b.z; s[0][3] += a.x * b.w;
            s[1][0] += a.y * b.x; s[1][1] += a.y * b.y; s[1][2] += a.y * b.z; s[1][3] += a.y * b.w;
            s[2][0] += a.z * b.x; s[2][1] += a.z * b.y; s[2][2] += a.z * b.z; s[2][3] += a.z * b.w;
            s[3][0] += a.w * b.x; s[3][1] += a.w * b.y; s[3][2] += a.w * b.z; s[3][3] += a.w * b.w;
        }
        // store transposed raw scores: Pt[j][i]
        #pragma unroll
        for (int c = 0; c < 4; c++) {
            float4 v = make_float4(s[0][c], s[1][c], s[2][c], s[3][c]);
            *(float4*)&Pt[(ty * 4 + c) * 68 + tx * 4] = v;
        }
        __syncthreads();

        // per-row online softmax pass (threads 0..63, one row each)
        if (tid < 64) {
            const int i = tid;
            float m_old = mrow[i];
            float tmax = -1e30f;
            #pragma unroll 8
            for (int j = 0; j < 64; j++) tmax = fmaxf(tmax, Pt[j * 68 + i]);
            float m_new = fmaxf(m_old, tmax);
            float corr  = __expf(m_old - m_new);
            float sum = 0.f;
            #pragma unroll 8
            for (int j = 0; j < 64; j++) {
                float e = __expf(Pt[j * 68 + i] - m_new);
                Pt[j * 68 + i] = e;
                sum += e;
            }
            lrow[i] = lrow[i] * corr + sum;
            mrow[i] = m_new;
            crow[i] = corr;
        }
        __syncthreads();

        // rescale accumulators
        #pragma unroll
        for (int r = 0; r < 4; r++) {
            float cf = crow[tx * 4 + r];
            #pragma unroll
            for (int c = 0; c < 16; c++) o[r][c] *= cf;
        }
        // O += P @ V
        #pragma unroll 2
        for (int j = 0; j < 64; j++) {
            float4 a  = *(const float4*)&Pt[j * 68 + tx * 4];
            const float* vrow = &Vs[j * 264 + ty * 16];
            float4 b0 = *(const float4*)&vrow[0];
            float4 b1 = *(const float4*)&vrow[4];
            float4 b2 = *(const float4*)&vrow[8];
            float4 b3 = *(const float4*)&vrow[12];
            float av[4] = {a.x, a.y, a.z, a.w};
            #pragma unroll
            for (int r = 0; r < 4; r++) {
                o[r][0]  += av[r] * b0.x; o[r][1]  += av[r] * b0.y;
                o[r][2]  += av[r] * b0.z; o[r][3]  += av[r] * b0.w;
                o[r][4]  += av[r] * b1.x; o[r][5]  += av[r] * b1.y;
                o[r][6]  += av[r] * b1.z; o[r][7]  += av[r] * b1.w;
                o[r][8]  += av[r] * b2.x; o[r][9]  += av[r] * b2.y;
                o[r][10] += av[r] * b2.z; o[r][11] += av[r] * b2.w;
                o[r][12] += av[r] * b3.x; o[r][13] += av[r] * b3.y;
                o[r][14] += av[r] * b3.z; o[r][15] += av[r] * b3.w;
            }
        }
        // next iteration's loads overwrite Ks/Vs/Pt -> sync at loop top
        __syncthreads();
    }

    // normalize + write out[n][c][i]
    #pragma unroll
    for (int r = 0; r < 4; r++) {
        float inv = 1.f / lrow[tx * 4 + r];
        int i = i0g + tx * 4 + r;
        #pragma unroll
        for (int c = 0; c < 16; c++) {
            int ch = ty * 16 + c;
            out[((size_t)n * C + ch) * HW + i] = o[r][c] * inv;
        }
    }
}

extern "C" void kernel_launch(void* const* d_in, const int* in_sizes, int n_in,
                              void* d_out, int out_size)
{
    const float* x  = (const float*)d_in[0];
    const float* Wq = (const float*)d_in[1];
    const float* bq = (const float*)d_in[2];
    const float* Wk = (const float*)d_in[3];
    const float* bk = (const float*)d_in[4];
    const float* Wv = (const float*)d_in[5];
    const float* bv = (const float*)d_in[6];
    float* out = (float*)d_out;

    dim3 pg(5, 64, NB);
    proj_kernel<<<pg, 256>>>(x, Wq, bq, Wk, bk, Wv, bv);

    static int smem_set = 0;
    int smem_bytes = SM_TOT * sizeof(float);
    cudaFuncSetAttribute(flash_kernel, cudaFuncAttributeMaxDynamicSharedMemorySize, smem_bytes);
    (void)smem_set;

    dim3 fg(HW / BM, NB);
    flash_kernel<<<fg, 256, smem_bytes>>>(out);
}

// round 4
// speedup vs baseline: 2.8106x; 2.8106x over previous
#include <cuda_runtime.h>
#include <cstdint>

#define NB   4
#define C    256
#define HW   4096
#define BM   128
#define BN   64

// Scratch: qkT[n][s][0..31]=q, [32..63]=k (tf32-rounded); vN[n][c][s] (tf32-rounded)
__device__ float g_qkT[NB * HW * 64];
__device__ float g_vN [NB * C * HW];

__device__ __forceinline__ float to_tf32(float x) {
    unsigned u; asm("cvt.rna.tf32.f32 %0, %1;" : "=r"(u) : "f"(x));
    return __uint_as_float(u);
}
__device__ __forceinline__ uint32_t smem_u32(const void* p) {
    uint32_t a;
    asm("{ .reg .u64 t; cvta.to.shared.u64 t, %1; cvt.u32.u64 %0, t; }" : "=r"(a) : "l"(p));
    return a;
}
__device__ __forceinline__ void cp16(uint32_t d, const void* s) {
    asm volatile("cp.async.cg.shared.global [%0], [%1], 16;" :: "r"(d), "l"(s));
}
#define CP_COMMIT() asm volatile("cp.async.commit_group;")
#define CP_WAIT(n)  asm volatile("cp.async.wait_group %0;" :: "n"(n))

// mma.sync m16n8k8 tf32: d += a*b
__device__ __forceinline__ void mma8(float* d, const float* a, float b0, float b1) {
    asm volatile(
        "mma.sync.aligned.m16n8k8.row.col.f32.tf32.tf32.f32 "
        "{%0,%1,%2,%3}, {%4,%5,%6,%7}, {%8,%9}, {%0,%1,%2,%3};"
        : "+f"(d[0]), "+f"(d[1]), "+f"(d[2]), "+f"(d[3])
        : "r"(__float_as_uint(a[0])), "r"(__float_as_uint(a[1])),
          "r"(__float_as_uint(a[2])), "r"(__float_as_uint(a[3])),
          "r"(__float_as_uint(b0)), "r"(__float_as_uint(b1)));
}

// ---------------------------------------------------------------------------
// Kernel 1: fused projections (SIMT fp32). O[320,4096] = W[320,256] @ X + b
// ---------------------------------------------------------------------------
__global__ __launch_bounds__(256) void proj_kernel(
    const float* __restrict__ x,
    const float* __restrict__ Wq, const float* __restrict__ bq,
    const float* __restrict__ Wk, const float* __restrict__ bk,
    const float* __restrict__ Wv, const float* __restrict__ bv)
{
    const int ot = blockIdx.x;          // 0..4
    const int st = blockIdx.y;          // 0..63
    const int n  = blockIdx.z;
    const int s0 = st * 64;
    const int r0g = ot * 64;

    __shared__ float Ws[32][68];        // [k][r]
    __shared__ float Xs[32][68];        // [k][s]

    const int tid = threadIdx.x;
    const int tx = tid & 15;            // s block
    const int ty = tid >> 4;            // r block

    float o[4][4];
    #pragma unroll
    for (int a = 0; a < 4; a++)
        #pragma unroll
        for (int b = 0; b < 4; b++) o[a][b] = 0.f;

    const float* xb = x + (size_t)n * C * HW;

    for (int k0 = 0; k0 < 256; k0 += 32) {
        for (int idx = tid; idx < 64 * 32; idx += 256) {
            int r = idx >> 5, c = idx & 31;
            int R = r0g + r;
            float w;
            if (R < 32)       w = Wq[R * 256 + k0 + c];
            else if (R < 64)  w = Wk[(R - 32) * 256 + k0 + c];
            else              w = Wv[(R - 64) * 256 + k0 + c];
            Ws[c][r] = w;
        }
        for (int idx = tid; idx < 32 * 64; idx += 256) {
            int c = idx >> 6, s = idx & 63;
            Xs[c][s] = xb[(size_t)(k0 + c) * HW + s0 + s];
        }
        __syncthreads();
        #pragma unroll 8
        for (int c = 0; c < 32; c++) {
            float4 a = *(const float4*)&Ws[c][ty * 4];   // r
            float4 b = *(const float4*)&Xs[c][tx * 4];   // s
            o[0][0] += b.x * a.x; o[0][1] += b.x * a.y; o[0][2] += b.x * a.z; o[0][3] += b.x * a.w;
            o[1][0] += b.y * a.x; o[1][1] += b.y * a.y; o[1][2] += b.y * a.z; o[1][3] += b.y * a.w;
            o[2][0] += b.z * a.x; o[2][1] += b.z * a.y; o[2][2] += b.z * a.z; o[2][3] += b.z * a.w;
            o[3][0] += b.w * a.x; o[3][1] += b.w * a.y; o[3][2] += b.w * a.z; o[3][3] += b.w * a.w;
        }
        __syncthreads();
    }

    float bias[4];
    #pragma unroll
    for (int rr = 0; rr < 4; rr++) {
        int R = r0g + ty * 4 + rr;
        if (R < 32)      bias[rr] = bq[R];
        else if (R < 64) bias[rr] = bk[R - 32];
        else             bias[rr] = bv[R - 64];
    }

    if (ot == 0) {
        #pragma unroll
        for (int ss = 0; ss < 4; ss++) {
            int s = s0 + tx * 4 + ss;
            float4 v = make_float4(to_tf32(o[ss][0] + bias[0]), to_tf32(o[ss][1] + bias[1]),
                                   to_tf32(o[ss][2] + bias[2]), to_tf32(o[ss][3] + bias[3]));
            *(float4*)&g_qkT[((size_t)n * HW + s) * 64 + ty * 4] = v;
        }
    } else {
        #pragma unroll
        for (int rr = 0; rr < 4; rr++) {
            int ch = (ot - 1) * 64 + ty * 4 + rr;
            float4 v = make_float4(to_tf32(o[0][rr] + bias[rr]), to_tf32(o[1][rr] + bias[rr]),
                                   to_tf32(o[2][rr] + bias[rr]), to_tf32(o[3][rr] + bias[rr]));
            *(float4*)&g_vN[((size_t)n * C + ch) * HW + s0 + tx * 4] = v;
        }
    }
}

// ---------------------------------------------------------------------------
// Kernel 2: mma.sync tf32 flash attention.
// BM=128 q rows/CTA, 256 threads (8 warps), grid (32, 4) = 128 CTAs.
// ---------------------------------------------------------------------------
#define VS_OFF(b)  ((b) * 69632)                 // 256*68*4
#define KS_OFF(b)  (139264 + (b) * 9216)         // 64*36*4
#define PS_OFF     157696                        // 128*66*4 = 33792
#define CROW_OFF   191488
#define LROW_OFF   192000
#define SM_BYTES   192512

__global__ __launch_bounds__(256, 1) void flash_mma(float* __restrict__ out)
{
    extern __shared__ char smem[];
    const uint32_t sb = smem_u32(smem);
    float* Pv   = (float*)(smem + PS_OFF);
    float* crow = (float*)(smem + CROW_OFF);
    float* lrow = (float*)(smem + LROW_OFF);

    const int tid  = threadIdx.x;
    const int w    = tid >> 5;
    const int lane = tid & 31;
    const int gid  = lane >> 2;   // groupID
    const int tig  = lane & 3;    // thread-in-group
    const int n    = blockIdx.y;
    const int i0g  = blockIdx.x * BM;

    const float* qkT = g_qkT + (size_t)n * HW * 64;
    const float* vN  = g_vN  + (size_t)n * C * HW;

    // ---- Q fragments: warp w owns rows 16w..16w+15 ----
    float qa[4][4];
    {
        const int r = i0g + w * 16 + gid;
        #pragma unroll
        for (int ks = 0; ks < 4; ks++) {
            const int k = ks * 8 + tig;
            qa[ks][0] = qkT[(size_t)r * 64 + k];
            qa[ks][1] = qkT[(size_t)(r + 8) * 64 + k];
            qa[ks][2] = qkT[(size_t)r * 64 + k + 4];
            qa[ks][3] = qkT[(size_t)(r + 8) * 64 + k + 4];
        }
    }

    float o[4][8][4];   // [mt][nt][frag]
    #pragma unroll
    for (int mt = 0; mt < 4; mt++)
        #pragma unroll
        for (int nt = 0; nt < 8; nt++)
            #pragma unroll
            for (int k = 0; k < 4; k++) o[mt][nt][k] = 0.f;

    float m0 = -1e30f, m1 = -1e30f, l0 = 0.f, l1 = 0.f;

    // ---- tile loader (K: 64x32 = 512 chunks, V: 256x64 = 4096 chunks) ----
    auto load_tiles = [&](int jt, int buf) {
        const uint32_t kd = sb + KS_OFF(buf);
        #pragma unroll
        for (int t = 0; t < 2; t++) {
            int idx = tid + t * 256;
            int j = idx >> 3, k4 = idx & 7;
            cp16(kd + j * 144 + k4 * 16, qkT + (size_t)(jt * 64 + j) * 64 + 32 + k4 * 4);
        }
        const uint32_t vd = sb + VS_OFF(buf);
        #pragma unroll
        for (int t = 0; t < 16; t++) {            // FIX: full 256x64 tile
            int idx = tid + t * 256;
            int c = idx >> 4, j4 = idx & 15;
            cp16(vd + c * 272 + j4 * 16, vN + (size_t)c * HW + jt * 64 + j4 * 4);
        }
        CP_COMMIT();
    };

    load_tiles(0, 0);

    const int rg = w >> 2, cg = w & 3;

    for (int jt = 0; jt < 64; jt++) {
        const int cur = jt & 1;
        if (jt < 63) { load_tiles(jt + 1, cur ^ 1); CP_WAIT(1); }
        else         { CP_WAIT(0); }
        __syncthreads();

        const float* Ks = (const float*)(smem + KS_OFF(cur));
        const float* Vs = (const float*)(smem + VS_OFF(cur));

        // ---- QK: S[16, 64] per warp ----
        float s[8][4];
        #pragma unroll
        for (int nt = 0; nt < 8; nt++)
            #pragma unroll
            for (int k = 0; k < 4; k++) s[nt][k] = 0.f;

        #pragma unroll
        for (int ks = 0; ks < 4; ks++) {
            #pragma unroll
            for (int nt = 0; nt < 8; nt++) {
                const float* kp = &Ks[(nt * 8 + gid) * 36 + ks * 8 + tig];
                float b0 = kp[0], b1 = kp[4];
                mma8(s[nt], qa[ks], b0, b1);
            }
        }

        // ---- online softmax ----
        float mx0 = -1e30f, mx1 = -1e30f;
        #pragma unroll
        for (int nt = 0; nt < 8; nt++) {
            mx0 = fmaxf(mx0, fmaxf(s[nt][0], s[nt][1]));
            mx1 = fmaxf(mx1, fmaxf(s[nt][2], s[nt][3]));
        }
        mx0 = fmaxf(mx0, __shfl_xor_sync(0xffffffffu, mx0, 1));
        mx0 = fmaxf(mx0, __shfl_xor_sync(0xffffffffu, mx0, 2));
        mx1 = fmaxf(mx1, __shfl_xor_sync(0xffffffffu, mx1, 1));
        mx1 = fmaxf(mx1, __shfl_xor_sync(0xffffffffu, mx1, 2));
        const float mn0 = fmaxf(m0, mx0), mn1 = fmaxf(m1, mx1);
        const float cr0 = __expf(m0 - mn0), cr1 = __expf(m1 - mn1);
        float sum0 = 0.f, sum1 = 0.f;
        #pragma unroll
        for (int nt = 0; nt < 8; nt++) {
            float p0 = __expf(s[nt][0] - mn0); sum0 += p0; s[nt][0] = to_tf32(p0);
            float p1 = __expf(s[nt][1] - mn0); sum0 += p1; s[nt][1] = to_tf32(p1);
            float p2 = __expf(s[nt][2] - mn1); sum1 += p2; s[nt][2] = to_tf32(p2);
            float p3 = __expf(s[nt][3] - mn1); sum1 += p3; s[nt][3] = to_tf32(p3);
        }
        sum0 += __shfl_xor_sync(0xffffffffu, sum0, 1);
        sum0 += __shfl_xor_sync(0xffffffffu, sum0, 2);
        sum1 += __shfl_xor_sync(0xffffffffu, sum1, 1);
        sum1 += __shfl_xor_sync(0xffffffffu, sum1, 2);
        l0 = l0 * cr0 + sum0;  m0 = mn0;
        l1 = l1 * cr1 + sum1;  m1 = mn1;
        if (tig == 0) {
            crow[w * 16 + gid]     = cr0;
            crow[w * 16 + gid + 8] = cr1;
        }
        const int pr0 = w * 16 + gid;
        #pragma unroll
        for (int nt = 0; nt < 8; nt++) {
            *(float2*)&Pv[pr0 * 66 + nt * 8 + 2 * tig]       = make_float2(s[nt][0], s[nt][1]);
            *(float2*)&Pv[(pr0 + 8) * 66 + nt * 8 + 2 * tig] = make_float2(s[nt][2], s[nt][3]);
        }
        __syncthreads();

        // ---- PV: O[64,64] per warp ----
        float cf[4][2];
        #pragma unroll
        for (int mt = 0; mt < 4; mt++) {
            cf[mt][0] = crow[rg * 64 + mt * 16 + gid];
            cf[mt][1] = crow[rg * 64 + mt * 16 + gid + 8];
        }
        #pragma unroll
        for (int mt = 0; mt < 4; mt++)
            #pragma unroll
            for (int nt = 0; nt < 8; nt++) {
                o[mt][nt][0] *= cf[mt][0]; o[mt][nt][1] *= cf[mt][0];
                o[mt][nt][2] *= cf[mt][1]; o[mt][nt][3] *= cf[mt][1];
            }

        #pragma unroll
        for (int ks = 0; ks < 8; ks++) {
            float a[4][4];
            #pragma unroll
            for (int mt = 0; mt < 4; mt++) {
                const float* pp = &Pv[(rg * 64 + mt * 16 + gid) * 66 + ks * 8 + tig];
                a[mt][0] = pp[0];
                a[mt][1] = pp[8 * 66];
                a[mt][2] = pp[4];
                a[mt][3] = pp[8 * 66 + 4];
            }
            #pragma unroll
            for (int nt = 0; nt < 8; nt++) {
                const float* vp = &Vs[(cg * 64 + nt * 8 + gid) * 68 + ks * 8 + tig];
                float b0 = vp[0], b1 = vp[4];
                #pragma unroll
                for (int mt = 0; mt < 4; mt++)
                    mma8(o[mt][nt], a[mt], b0, b1);
            }
        }
        __syncthreads();
    }

    // ---- epilogue ----
    if (tig == 0) {
        lrow[w * 16 + gid]     = l0;
        lrow[w * 16 + gid + 8] = l1;
    }
    __syncthreads();

    float inv[4][2];
    #pragma unroll
    for (int mt = 0; mt < 4; mt++) {
        inv[mt][0] = 1.f / lrow[rg * 64 + mt * 16 + gid];
        inv[mt][1] = 1.f / lrow[rg * 64 + mt * 16 + gid + 8];
    }

    float* Os = (float*)smem;   // [128][257] staging
    #pragma unroll
    for (int mt = 0; mt < 4; mt++)
        #pragma unroll
        for (int nt = 0; nt < 8; nt++)
            #pragma unroll
            for (int k = 0; k < 4; k++) {
                int r = rg * 64 + mt * 16 + gid + 8 * (k >> 1);
                int c = cg * 64 + nt * 8 + 2 * tig + (k & 1);
                Os[r * 257 + c] = o[mt][nt][k] * inv[mt][k >> 1];
            }
    __syncthreads();

    const int i   = tid & 127;
    const int ch0 = (tid >> 7) * 128;
    #pragma unroll 4
    for (int cc = 0; cc < 128; cc++) {
        int c = ch0 + cc;
        out[((size_t)n * C + c) * HW + i0g + i] = Os[i * 257 + c];
    }
}

extern "C" void kernel_launch(void* const* d_in, const int* in_sizes, int n_in,
                              void* d_out, int out_size)
{
    const float* x  = (const float*)d_in[0];
    const float* Wq = (const float*)d_in[1];
    const float* bq = (const float*)d_in[2];
    const float* Wk = (const float*)d_in[3];
    const float* bk = (const float*)d_in[4];
    const float* Wv = (const float*)d_in[5];
    const float* bv = (const float*)d_in[6];
    float* out = (float*)d_out;

    dim3 pg(5, 64, NB);
    proj_kernel<<<pg, 256>>>(x, Wq, bq, Wk, bk, Wv, bv);

    cudaFuncSetAttribute(flash_mma, cudaFuncAttributeMaxDynamicSharedMemorySize, SM_BYTES);
    dim3 fg(HW / BM, NB);
    flash_mma<<<fg, 256, SM_BYTES>>>(out);
}

// round 5
// speedup vs baseline: 4.2111x; 1.4983x over previous
#include <cuda_runtime.h>
#include <cuda_fp16.h>
#include <cstdint>

#define NB   4
#define C    256
#define HW   4096
#define BM   128
#define BN   64

// Scratch (fp16): qkh[n][s][0..31]=q, [32..63]=k ; vh[n][c][s]
__device__ __half g_qkh[NB * HW * 64];
__device__ __half g_vh [NB * C * HW];

__device__ __forceinline__ uint32_t smem_u32(const void* p) {
    uint32_t a;
    asm("{ .reg .u64 t; cvta.to.shared.u64 t, %1; cvt.u32.u64 %0, t; }" : "=r"(a) : "l"(p));
    return a;
}
__device__ __forceinline__ void cp16(uint32_t d, const void* s) {
    asm volatile("cp.async.cg.shared.global [%0], [%1], 16;" :: "r"(d), "l"(s));
}
#define CP_COMMIT() asm volatile("cp.async.commit_group;")
#define CP_WAIT(n)  asm volatile("cp.async.wait_group %0;" :: "n"(n))

// mma.sync m16n8k16 fp16 inputs, fp32 accum: d += a*b
__device__ __forceinline__ void mma16(float* d, const uint32_t* a, uint32_t b0, uint32_t b1) {
    asm volatile(
        "mma.sync.aligned.m16n8k16.row.col.f32.f16.f16.f32 "
        "{%0,%1,%2,%3}, {%4,%5,%6,%7}, {%8,%9}, {%0,%1,%2,%3};"
        : "+f"(d[0]), "+f"(d[1]), "+f"(d[2]), "+f"(d[3])
        : "r"(a[0]), "r"(a[1]), "r"(a[2]), "r"(a[3]), "r"(b0), "r"(b1));
}

// ---------------------------------------------------------------------------
// Kernel 1: fused projections (SIMT fp32), outputs fp16.
// ---------------------------------------------------------------------------
__global__ __launch_bounds__(256) void proj_kernel(
    const float* __restrict__ x,
    const float* __restrict__ Wq, const float* __restrict__ bq,
    const float* __restrict__ Wk, const float* __restrict__ bk,
    const float* __restrict__ Wv, const float* __restrict__ bv)
{
    const int ot = blockIdx.x;          // 0..4
    const int st = blockIdx.y;          // 0..63
    const int n  = blockIdx.z;
    const int s0 = st * 64;
    const int r0g = ot * 64;

    __shared__ float Ws[32][68];        // [k][r]
    __shared__ float Xs[32][68];        // [k][s]

    const int tid = threadIdx.x;
    const int tx = tid & 15;            // s block
    const int ty = tid >> 4;            // r block

    float o[4][4];
    #pragma unroll
    for (int a = 0; a < 4; a++)
        #pragma unroll
        for (int b = 0; b < 4; b++) o[a][b] = 0.f;

    const float* xb = x + (size_t)n * C * HW;

    for (int k0 = 0; k0 < 256; k0 += 32) {
        for (int idx = tid; idx < 64 * 32; idx += 256) {
            int r = idx >> 5, c = idx & 31;
            int R = r0g + r;
            float w;
            if (R < 32)       w = Wq[R * 256 + k0 + c];
            else if (R < 64)  w = Wk[(R - 32) * 256 + k0 + c];
            else              w = Wv[(R - 64) * 256 + k0 + c];
            Ws[c][r] = w;
        }
        for (int idx = tid; idx < 32 * 64; idx += 256) {
            int c = idx >> 6, s = idx & 63;
            Xs[c][s] = xb[(size_t)(k0 + c) * HW + s0 + s];
        }
        __syncthreads();
        #pragma unroll 8
        for (int c = 0; c < 32; c++) {
            float4 a = *(const float4*)&Ws[c][ty * 4];   // r
            float4 b = *(const float4*)&Xs[c][tx * 4];   // s
            o[0][0] += b.x * a.x; o[0][1] += b.x * a.y; o[0][2] += b.x * a.z; o[0][3] += b.x * a.w;
            o[1][0] += b.y * a.x; o[1][1] += b.y * a.y; o[1][2] += b.y * a.z; o[1][3] += b.y * a.w;
            o[2][0] += b.z * a.x; o[2][1] += b.z * a.y; o[2][2] += b.z * a.z; o[2][3] += b.z * a.w;
            o[3][0] += b.w * a.x; o[3][1] += b.w * a.y; o[3][2] += b.w * a.z; o[3][3] += b.w * a.w;
        }
        __syncthreads();
    }

    float bias[4];
    #pragma unroll
    for (int rr = 0; rr < 4; rr++) {
        int R = r0g + ty * 4 + rr;
        if (R < 32)      bias[rr] = bq[R];
        else if (R < 64) bias[rr] = bk[R - 32];
        else             bias[rr] = bv[R - 64];
    }

    if (ot == 0) {
        // qk: [s][r] fp16
        #pragma unroll
        for (int ss = 0; ss < 4; ss++) {
            int s = s0 + tx * 4 + ss;
            __half2 h01 = __floats2half2_rn(o[ss][0] + bias[0], o[ss][1] + bias[1]);
            __half2 h23 = __floats2half2_rn(o[ss][2] + bias[2], o[ss][3] + bias[3]);
            uint2 pk = make_uint2(*(uint32_t*)&h01, *(uint32_t*)&h23);
            *(uint2*)&g_qkh[((size_t)n * HW + s) * 64 + ty * 4] = pk;
        }
    } else {
        // v: [c][s] fp16 (s contiguous)
        #pragma unroll
        for (int rr = 0; rr < 4; rr++) {
            int ch = (ot - 1) * 64 + ty * 4 + rr;
            __half2 h01 = __floats2half2_rn(o[0][rr] + bias[rr], o[1][rr] + bias[rr]);
            __half2 h23 = __floats2half2_rn(o[2][rr] + bias[rr], o[3][rr] + bias[rr]);
            uint2 pk = make_uint2(*(uint32_t*)&h01, *(uint32_t*)&h23);
            *(uint2*)&g_vh[((size_t)n * C + ch) * HW + s0 + tx * 4] = pk;
        }
    }
}

// ---------------------------------------------------------------------------
// Kernel 2: fp16 m16n8k16 flash attention.
// BM=128 q rows/CTA, 256 threads (8 warps), grid (32, 4) = 128 CTAs.
// smem (halfs, padded strides for conflict-free quad access):
//   Vs[buf][256][72], Ks[buf][64][40], Pv[128][72], crow/lrow fp32[128]
// ---------------------------------------------------------------------------
#define VS_STRIDE 72
#define KS_STRIDE 40
#define PS_STRIDE 72
#define VS_OFF(b) ((b) * 36864)                  // 256*72*2
#define KS_OFF(b) (73728 + (b) * 5120)           // 64*40*2
#define PS_OFF    83968                          // 128*72*2 = 18432
#define CROW_OFF  102400
#define LROW_OFF  102912
#define SM_BYTES  103424

__global__ __launch_bounds__(256, 1) void flash_fp16(float* __restrict__ out)
{
    extern __shared__ char smem[];
    const uint32_t sb = smem_u32(smem);
    __half* Pv   = (__half*)(smem + PS_OFF);
    float*  crow = (float*)(smem + CROW_OFF);
    float*  lrow = (float*)(smem + LROW_OFF);

    const int tid  = threadIdx.x;
    const int w    = tid >> 5;
    const int lane = tid & 31;
    const int gid  = lane >> 2;
    const int tig  = lane & 3;
    const int n    = blockIdx.y;
    const int i0g  = blockIdx.x * BM;

    const __half* qkh = g_qkh + (size_t)n * HW * 64;
    const __half* vh  = g_vh  + (size_t)n * C * HW;

    // ---- Q A-fragments (k=32 -> 2 ksteps of k16): warp w owns rows 16w..16w+15
    uint32_t qa[2][4];
    {
        const int r = i0g + w * 16 + gid;
        #pragma unroll
        for (int kk = 0; kk < 2; kk++) {
            const int c = kk * 16 + 2 * tig;
            qa[kk][0] = *(const uint32_t*)&qkh[(size_t)r * 64 + c];
            qa[kk][1] = *(const uint32_t*)&qkh[(size_t)(r + 8) * 64 + c];
            qa[kk][2] = *(const uint32_t*)&qkh[(size_t)r * 64 + c + 8];
            qa[kk][3] = *(const uint32_t*)&qkh[(size_t)(r + 8) * 64 + c + 8];
        }
    }

    float o[4][8][4];
    #pragma unroll
    for (int mt = 0; mt < 4; mt++)
        #pragma unroll
        for (int nt = 0; nt < 8; nt++)
            #pragma unroll
            for (int k = 0; k < 4; k++) o[mt][nt][k] = 0.f;

    float m0 = -1e30f, m1 = -1e30f, l0 = 0.f, l1 = 0.f;

    // ---- tile loader: K 64x32 fp16 (256 chunks), V 256x64 fp16 (2048 chunks)
    auto load_tiles = [&](int jt, int buf) {
        const uint32_t kd = sb + KS_OFF(buf);
        {
            int j = tid >> 2, k8 = tid & 3;
            cp16(kd + j * (KS_STRIDE * 2) + k8 * 16,
                 qkh + (size_t)(jt * 64 + j) * 64 + 32 + k8 * 8);
        }
        const uint32_t vd = sb + VS_OFF(buf);
        #pragma unroll
        for (int t = 0; t < 8; t++) {
            int idx = tid + t * 256;
            int c = idx >> 3, j8 = idx & 7;
            cp16(vd + c * (VS_STRIDE * 2) + j8 * 16,
                 vh + (size_t)c * HW + jt * 64 + j8 * 8);
        }
        CP_COMMIT();
    };

    load_tiles(0, 0);

    const int rg = w >> 2, cg = w & 3;

    for (int jt = 0; jt < 64; jt++) {
        const int cur = jt & 1;
        if (jt < 63) { load_tiles(jt + 1, cur ^ 1); CP_WAIT(1); }
        else         { CP_WAIT(0); }
        __syncthreads();

        const __half* Ks = (const __half*)(smem + KS_OFF(cur));
        const __half* Vs = (const __half*)(smem + VS_OFF(cur));

        // ---- QK: S[16, 64] per warp ----
        float s[8][4];
        #pragma unroll
        for (int nt = 0; nt < 8; nt++)
            #pragma unroll
            for (int k = 0; k < 4; k++) s[nt][k] = 0.f;

        #pragma unroll
        for (int kk = 0; kk < 2; kk++) {
            #pragma unroll
            for (int nt = 0; nt < 8; nt++) {
                const __half* kp = &Ks[(nt * 8 + gid) * KS_STRIDE + kk * 16 + 2 * tig];
                uint32_t b0 = *(const uint32_t*)kp;
                uint32_t b1 = *(const uint32_t*)(kp + 8);
                mma16(s[nt], qa[kk], b0, b1);
            }
        }

        // ---- online softmax (rows r0 = 16w+gid, r1 = +8) ----
        float mx0 = -1e30f, mx1 = -1e30f;
        #pragma unroll
        for (int nt = 0; nt < 8; nt++) {
            mx0 = fmaxf(mx0, fmaxf(s[nt][0], s[nt][1]));
            mx1 = fmaxf(mx1, fmaxf(s[nt][2], s[nt][3]));
        }
        mx0 = fmaxf(mx0, __shfl_xor_sync(0xffffffffu, mx0, 1));
        mx0 = fmaxf(mx0, __shfl_xor_sync(0xffffffffu, mx0, 2));
        mx1 = fmaxf(mx1, __shfl_xor_sync(0xffffffffu, mx1, 1));
        mx1 = fmaxf(mx1, __shfl_xor_sync(0xffffffffu, mx1, 2));
        const float mn0 = fmaxf(m0, mx0), mn1 = fmaxf(m1, mx1);
        const float cr0 = __expf(m0 - mn0), cr1 = __expf(m1 - mn1);
        float sum0 = 0.f, sum1 = 0.f;
        const int pr0 = w * 16 + gid;
        #pragma unroll
        for (int nt = 0; nt < 8; nt++) {
            float p0 = __expf(s[nt][0] - mn0); sum0 += p0;
            float p1 = __expf(s[nt][1] - mn0); sum0 += p1;
            float p2 = __expf(s[nt][2] - mn1); sum1 += p2;
            float p3 = __expf(s[nt][3] - mn1); sum1 += p3;
            __half2 h01 = __floats2half2_rn(p0, p1);
            __half2 h23 = __floats2half2_rn(p2, p3);
            *(uint32_t*)&Pv[pr0 * PS_STRIDE + nt * 8 + 2 * tig]       = *(uint32_t*)&h01;
            *(uint32_t*)&Pv[(pr0 + 8) * PS_STRIDE + nt * 8 + 2 * tig] = *(uint32_t*)&h23;
        }
        sum0 += __shfl_xor_sync(0xffffffffu, sum0, 1);
        sum0 += __shfl_xor_sync(0xffffffffu, sum0, 2);
        sum1 += __shfl_xor_sync(0xffffffffu, sum1, 1);
        sum1 += __shfl_xor_sync(0xffffffffu, sum1, 2);
        l0 = l0 * cr0 + sum0;  m0 = mn0;
        l1 = l1 * cr1 + sum1;  m1 = mn1;
        if (tig == 0) {
            crow[w * 16 + gid]     = cr0;
            crow[w * 16 + gid + 8] = cr1;
        }
        __syncthreads();

        // ---- PV: O[64,64] per warp, rescale then accumulate ----
        float cf[4][2];
        #pragma unroll
        for (int mt = 0; mt < 4; mt++) {
            cf[mt][0] = crow[rg * 64 + mt * 16 + gid];
            cf[mt][1] = crow[rg * 64 + mt * 16 + gid + 8];
        }
        #pragma unroll
        for (int mt = 0; mt < 4; mt++)
            #pragma unroll
            for (int nt = 0; nt < 8; nt++) {
                o[mt][nt][0] *= cf[mt][0]; o[mt][nt][1] *= cf[mt][0];
                o[mt][nt][2] *= cf[mt][1]; o[mt][nt][3] *= cf[mt][1];
            }

        #pragma unroll
        for (int kk = 0; kk < 4; kk++) {
            uint32_t a[4][4];
            #pragma unroll
            for (int mt = 0; mt < 4; mt++) {
                const __half* pp = &Pv[(rg * 64 + mt * 16 + gid) * PS_STRIDE + kk * 16 + 2 * tig];
                a[mt][0] = *(const uint32_t*)pp;
                a[mt][1] = *(const uint32_t*)(pp + 8 * PS_STRIDE);
                a[mt][2] = *(const uint32_t*)(pp + 8);
                a[mt][3] = *(const uint32_t*)(pp + 8 * PS_STRIDE + 8);
            }
            #pragma unroll
            for (int nt = 0; nt < 8; nt++) {
                const __half* vp = &Vs[(cg * 64 + nt * 8 + gid) * VS_STRIDE + kk * 16 + 2 * tig];
                uint32_t b0 = *(const uint32_t*)vp;
                uint32_t b1 = *(const uint32_t*)(vp + 8);
                #pragma unroll
                for (int mt = 0; mt < 4; mt++)
                    mma16(o[mt][nt], a[mt], b0, b1);
            }
        }
        __syncthreads();
    }

    // ---- epilogue: direct fragment stores, normalized ----
    if (tig == 0) {
        lrow[w * 16 + gid]     = l0;
        lrow[w * 16 + gid + 8] = l1;
    }
    __syncthreads();

    float inv[4][2];
    #pragma unroll
    for (int mt = 0; mt < 4; mt++) {
        inv[mt][0] = 1.f / lrow[rg * 64 + mt * 16 + gid];
        inv[mt][1] = 1.f / lrow[rg * 64 + mt * 16 + gid + 8];
    }

    #pragma unroll
    for (int mt = 0; mt < 4; mt++) {
        const int i_a = i0g + rg * 64 + mt * 16 + gid;
        const int i_b = i_a + 8;
        #pragma unroll
        for (int nt = 0; nt < 8; nt++) {
            const int c0 = cg * 64 + nt * 8 + 2 * tig;
            out[((size_t)n * C + c0) * HW + i_a]     = o[mt][nt][0] * inv[mt][0];
            out[((size_t)n * C + c0 + 1) * HW + i_a] = o[mt][nt][1] * inv[mt][0];
            out[((size_t)n * C + c0) * HW + i_b]     = o[mt][nt][2] * inv[mt][1];
            out[((size_t)n * C + c0 + 1) * HW + i_b] = o[mt][nt][3] * inv[mt][1];
        }
    }
}

extern "C" void kernel_launch(void* const* d_in, const int* in_sizes, int n_in,
                              void* d_out, int out_size)
{
    const float* x  = (const float*)d_in[0];
    const float* Wq = (const float*)d_in[1];
    const float* bq = (const float*)d_in[2];
    const float* Wk = (const float*)d_in[3];
    const float* bk = (const float*)d_in[4];
    const float* Wv = (const float*)d_in[5];
    const float* bv = (const float*)d_in[6];
    float* out = (float*)d_out;

    dim3 pg(5, 64, NB);
    proj_kernel<<<pg, 256>>>(x, Wq, bq, Wk, bk, Wv, bv);

    cudaFuncSetAttribute(flash_fp16, cudaFuncAttributeMaxDynamicSharedMemorySize, SM_BYTES);
    dim3 fg(HW / BM, NB);
    flash_fp16<<<fg, 256, SM_BYTES>>>(out);
}

// round 6
// speedup vs baseline: 6.6922x; 1.5892x over previous
#include <cuda_runtime.h>
#include <cuda_fp16.h>
#include <cstdint>

#define NB   4
#define C    256
#define HW   4096
#define BM   128
#define LOG2E 1.4426950408889634f

// fp16 staging
__device__ __half g_xh [NB * C * HW];        // [n][c][s]
__device__ __half g_Wh [320 * 256];          // rows 0-31 Wq, 32-63 Wk, 64-319 Wv
__device__ __half g_qkh[NB * HW * 64];       // [n][s][0..31]=q*log2e, [32..63]=k
__device__ __half g_vh [NB * C * HW];        // [n][c][s]

__device__ __forceinline__ uint32_t smem_u32(const void* p) {
    uint32_t a;
    asm("{ .reg .u64 t; cvta.to.shared.u64 t, %1; cvt.u32.u64 %0, t; }" : "=r"(a) : "l"(p));
    return a;
}
__device__ __forceinline__ void cp16(uint32_t d, const void* s) {
    asm volatile("cp.async.cg.shared.global [%0], [%1], 16;" :: "r"(d), "l"(s));
}
#define CP_COMMIT() asm volatile("cp.async.commit_group;")
#define CP_WAIT(n)  asm volatile("cp.async.wait_group %0;" :: "n"(n))

__device__ __forceinline__ float ex2f(float x) {
    float y; asm("ex2.approx.ftz.f32 %0, %1;" : "=f"(y) : "f"(x)); return y;
}

// mma.sync m16n8k16 fp16 in, fp32 accum
__device__ __forceinline__ void mma16(float* d, const uint32_t* a, uint32_t b0, uint32_t b1) {
    asm volatile(
        "mma.sync.aligned.m16n8k16.row.col.f32.f16.f16.f32 "
        "{%0,%1,%2,%3}, {%4,%5,%6,%7}, {%8,%9}, {%0,%1,%2,%3};"
        : "+f"(d[0]), "+f"(d[1]), "+f"(d[2]), "+f"(d[3])
        : "r"(a[0]), "r"(a[1]), "r"(a[2]), "r"(a[3]), "r"(b0), "r"(b1));
}
__device__ __forceinline__ void ldsm_x4(uint32_t* r, uint32_t addr) {
    asm volatile("ldmatrix.sync.aligned.m8n8.x4.shared.b16 {%0,%1,%2,%3}, [%4];"
        : "=r"(r[0]), "=r"(r[1]), "=r"(r[2]), "=r"(r[3]) : "r"(addr));
}
__device__ __forceinline__ void ldsm_x4_t(uint32_t* r, uint32_t addr) {
    asm volatile("ldmatrix.sync.aligned.m8n8.x4.trans.shared.b16 {%0,%1,%2,%3}, [%4];"
        : "=r"(r[0]), "=r"(r[1]), "=r"(r[2]), "=r"(r[3]) : "r"(addr));
}

// ---------------------------------------------------------------------------
// Kernel 0: convert x and W to fp16. grid 4096+80 blocks x 256.
// ---------------------------------------------------------------------------
__global__ __launch_bounds__(256) void convert_kernel(
    const float* __restrict__ x,
    const float* __restrict__ Wq, const float* __restrict__ Wk,
    const float* __restrict__ Wv)
{
    const int bid = blockIdx.x;
    const int tid = threadIdx.x;
    if (bid < 4096) {
        int idx = bid * 1024 + tid * 4;
        float4 v = *(const float4*)&x[idx];
        __half2 h01 = __floats2half2_rn(v.x, v.y);
        __half2 h23 = __floats2half2_rn(v.z, v.w);
        *(uint2*)&g_xh[idx] = make_uint2(*(uint32_t*)&h01, *(uint32_t*)&h23);
    } else {
        int idx = (bid - 4096) * 1024 + tid * 4;   // < 81920
        int R = idx >> 8, c = idx & 255;
        const float* src;
        if (R < 32)      src = Wq + R * 256 + c;
        else if (R < 64) src = Wk + (R - 32) * 256 + c;
        else             src = Wv + (R - 64) * 256 + c;
        float4 v = *(const float4*)src;
        __half2 h01 = __floats2half2_rn(v.x, v.y);
        __half2 h23 = __floats2half2_rn(v.z, v.w);
        *(uint2*)&g_Wh[idx] = make_uint2(*(uint32_t*)&h01, *(uint32_t*)&h23);
    }
}

// ---------------------------------------------------------------------------
// Kernel 1: fp16 mma projections. O[64,128] tile, K=256.
// grid (5 ot, 32 st, 4 n), block 256 (8 warps: wr=w&3 row16, wc=w>>2 col64).
// smem: Ws[64][264] (35KB resident), Xs double buf [32][136].
// ---------------------------------------------------------------------------
#define PW_STRIDE 264
#define PX_STRIDE 136
#define PWS_OFF   0
#define PXS_OFF(b) (34816 + (b) * 8704)
#define PROJ_SMEM 52224

__global__ __launch_bounds__(256, 1) void proj_mma(
    const float* __restrict__ bq, const float* __restrict__ bk,
    const float* __restrict__ bv)
{
    extern __shared__ char smem[];
    const uint32_t sb = smem_u32(smem);

    const int tid  = threadIdx.x;
    const int w    = tid >> 5;
    const int lane = tid & 31;
    const int gid  = lane >> 2;
    const int tig  = lane & 3;
    const int ot   = blockIdx.x;            // 0..4
    const int s0   = blockIdx.y * 128;
    const int n    = blockIdx.z;
    const int r0g  = ot * 64;
    const int rbase = (w & 3) * 16;
    const int cbase = (w >> 2) * 64;

    const __half* xh = g_xh + (size_t)n * C * HW;

    // ---- prologue loads ----
    // W tile [64][256] -> Ws (stride 264)
    #pragma unroll
    for (int t = 0; t < 8; t++) {
        int cid = tid + t * 256;
        int r = cid >> 5, kc = cid & 31;
        cp16(sb + PWS_OFF + r * (PW_STRIDE * 2) + kc * 16,
             g_Wh + (size_t)(r0g + r) * 256 + kc * 8);
    }
    // X chunk 0 -> buf 0  ([32 k][128 s], stride 136)
    #pragma unroll
    for (int t = 0; t < 2; t++) {
        int cid = tid + t * 256;
        int kr = cid >> 4, kc = cid & 15;
        cp16(sb + PXS_OFF(0) + kr * (PX_STRIDE * 2) + kc * 16,
             xh + (size_t)kr * HW + s0 + kc * 8);
    }
    CP_COMMIT();
    // X chunk 1 -> buf 1
    #pragma unroll
    for (int t = 0; t < 2; t++) {
        int cid = tid + t * 256;
        int kr = cid >> 4, kc = cid & 15;
        cp16(sb + PXS_OFF(1) + kr * (PX_STRIDE * 2) + kc * 16,
             xh + (size_t)(32 + kr) * HW + s0 + kc * 8);
    }
    CP_COMMIT();
    CP_WAIT(1);
    __syncthreads();

    float o[8][4];
    #pragma unroll
    for (int nt = 0; nt < 8; nt++)
        #pragma unroll
        for (int k = 0; k < 4; k++) o[nt][k] = 0.f;

    // ldmatrix lane addressing
    const int lrow = (lane & 7) + ((lane >> 3) & 1) * 8;   // within-tile row + tile row off
    const int lcol8 = ((lane >> 4) & 1) * 8;

    for (int c = 0; c < 8; c++) {
        const uint32_t xbuf = sb + PXS_OFF(c & 1);
        #pragma unroll
        for (int kk = 0; kk < 2; kk++) {
            const int k0 = c * 32 + kk * 16;
            uint32_t a[4];
            ldsm_x4(a, sb + PWS_OFF + ((rbase + lrow) * PW_STRIDE + k0 + lcol8) * 2);
            #pragma unroll
            for (int ntp = 0; ntp < 4; ntp++) {
                uint32_t b[4];
                ldsm_x4_t(b, xbuf + ((kk * 16 + lrow) * PX_STRIDE + cbase + ntp * 16 + lcol8) * 2);
                mma16(o[2 * ntp],     a, b[0], b[1]);
                mma16(o[2 * ntp + 1], a, b[2], b[3]);
            }
        }
        __syncthreads();
        if (c + 2 < 8) {
            #pragma unroll
            for (int t = 0; t < 2; t++) {
                int cid = tid + t * 256;
                int kr = cid >> 4, kc = cid & 15;
                cp16(sb + PXS_OFF(c & 1) + kr * (PX_STRIDE * 2) + kc * 16,
                     xh + (size_t)((c + 2) * 32 + kr) * HW + s0 + kc * 8);
            }
            CP_COMMIT();
        }
        if (c + 1 < 8) {
            if (c + 2 < 8) { CP_WAIT(1); } else { CP_WAIT(0); }
            __syncthreads();
        }
    }

    // ---- epilogue ----
    const int R0 = rbase + gid;            // local row 0..63
    const int R1 = R0 + 8;

    if (ot == 0) {
        float b0v = (R0 < 32) ? bq[R0] : bk[R0 - 32];
        float b1v = (R1 < 32) ? bq[R1] : bk[R1 - 32];
        float sc0 = (R0 < 32) ? LOG2E : 1.f;
        float sc1 = (R1 < 32) ? LOG2E : 1.f;
        #pragma unroll
        for (int nt = 0; nt < 8; nt++) {
            int s = s0 + cbase + nt * 8 + 2 * tig;
            __half v00 = __float2half_rn((o[nt][0] + b0v) * sc0);
            __half v01 = __float2half_rn((o[nt][1] + b0v) * sc0);
            __half v10 = __float2half_rn((o[nt][2] + b1v) * sc1);
            __half v11 = __float2half_rn((o[nt][3] + b1v) * sc1);
            g_qkh[((size_t)n * HW + s) * 64 + R0]     = v00;
            g_qkh[((size_t)n * HW + s + 1) * 64 + R0] = v01;
            g_qkh[((size_t)n * HW + s) * 64 + R1]     = v10;
            g_qkh[((size_t)n * HW + s + 1) * 64 + R1] = v11;
        }
    } else {
        int ch0 = r0g - 64 + R0;
        int ch1 = r0g - 64 + R1;
        float b0v = bv[ch0], b1v = bv[ch1];
        #pragma unroll
        for (int nt = 0; nt < 8; nt++) {
            int s = s0 + cbase + nt * 8 + 2 * tig;
            __half2 h0 = __floats2half2_rn(o[nt][0] + b0v, o[nt][1] + b0v);
            __half2 h1 = __floats2half2_rn(o[nt][2] + b1v, o[nt][3] + b1v);
            *(uint32_t*)&g_vh[((size_t)n * C + ch0) * HW + s] = *(uint32_t*)&h0;
            *(uint32_t*)&g_vh[((size_t)n * C + ch1) * HW + s] = *(uint32_t*)&h1;
        }
    }
}

// ---------------------------------------------------------------------------
// Kernel 2: fp16 m16n8k16 flash attention (exp2 softmax; q pre-scaled).
// ---------------------------------------------------------------------------
#define VS_STRIDE 72
#define KS_STRIDE 40
#define PS_STRIDE 72
#define VS_OFF(b) ((b) * 36864)
#define KS_OFF(b) (73728 + (b) * 5120)
#define PS_OFF    83968
#define CROW_OFF  102400
#define LROW_OFF  102912
#define SM_BYTES  103424

__global__ __launch_bounds__(256, 1) void flash_fp16(float* __restrict__ out)
{
    extern __shared__ char smem[];
    const uint32_t sb = smem_u32(smem);
    __half* Pv   = (__half*)(smem + PS_OFF);
    float*  crow = (float*)(smem + CROW_OFF);
    float*  lrow = (float*)(smem + LROW_OFF);

    const int tid  = threadIdx.x;
    const int w    = tid >> 5;
    const int lane = tid & 31;
    const int gid  = lane >> 2;
    const int tig  = lane & 3;
    const int n    = blockIdx.y;
    const int i0g  = blockIdx.x * BM;

    const __half* qkh = g_qkh + (size_t)n * HW * 64;
    const __half* vh  = g_vh  + (size_t)n * C * HW;

    uint32_t qa[2][4];
    {
        const int r = i0g + w * 16 + gid;
        #pragma unroll
        for (int kk = 0; kk < 2; kk++) {
            const int c = kk * 16 + 2 * tig;
            qa[kk][0] = *(const uint32_t*)&qkh[(size_t)r * 64 + c];
            qa[kk][1] = *(const uint32_t*)&qkh[(size_t)(r + 8) * 64 + c];
            qa[kk][2] = *(const uint32_t*)&qkh[(size_t)r * 64 + c + 8];
            qa[kk][3] = *(const uint32_t*)&qkh[(size_t)(r + 8) * 64 + c + 8];
        }
    }

    float o[4][8][4];
    #pragma unroll
    for (int mt = 0; mt < 4; mt++)
        #pragma unroll
        for (int nt = 0; nt < 8; nt++)
            #pragma unroll
            for (int k = 0; k < 4; k++) o[mt][nt][k] = 0.f;

    float m0 = -1e30f, m1 = -1e30f, l0 = 0.f, l1 = 0.f;

    auto load_tiles = [&](int jt, int buf) {
        const uint32_t kd = sb + KS_OFF(buf);
        {
            int j = tid >> 2, k8 = tid & 3;
            cp16(kd + j * (KS_STRIDE * 2) + k8 * 16,
                 qkh + (size_t)(jt * 64 + j) * 64 + 32 + k8 * 8);
        }
        const uint32_t vd = sb + VS_OFF(buf);
        #pragma unroll
        for (int t = 0; t < 8; t++) {
            int idx = tid + t * 256;
            int c = idx >> 3, j8 = idx & 7;
            cp16(vd + c * (VS_STRIDE * 2) + j8 * 16,
                 vh + (size_t)c * HW + jt * 64 + j8 * 8);
        }
        CP_COMMIT();
    };

    load_tiles(0, 0);

    const int rg = w >> 2, cg = w & 3;

    for (int jt = 0; jt < 64; jt++) {
        const int cur = jt & 1;
        if (jt < 63) { load_tiles(jt + 1, cur ^ 1); CP_WAIT(1); }
        else         { CP_WAIT(0); }
        __syncthreads();

        const __half* Ks = (const __half*)(smem + KS_OFF(cur));
        const __half* Vs = (const __half*)(smem + VS_OFF(cur));

        float s[8][4];
        #pragma unroll
        for (int nt = 0; nt < 8; nt++)
            #pragma unroll
            for (int k = 0; k < 4; k++) s[nt][k] = 0.f;

        #pragma unroll
        for (int kk = 0; kk < 2; kk++) {
            #pragma unroll
            for (int nt = 0; nt < 8; nt++) {
                const __half* kp = &Ks[(nt * 8 + gid) * KS_STRIDE + kk * 16 + 2 * tig];
                uint32_t b0 = *(const uint32_t*)kp;
                uint32_t b1 = *(const uint32_t*)(kp + 8);
                mma16(s[nt], qa[kk], b0, b1);
            }
        }

        float mx0 = -1e30f, mx1 = -1e30f;
        #pragma unroll
        for (int nt = 0; nt < 8; nt++) {
            mx0 = fmaxf(mx0, fmaxf(s[nt][0], s[nt][1]));
            mx1 = fmaxf(mx1, fmaxf(s[nt][2], s[nt][3]));
        }
        mx0 = fmaxf(mx0, __shfl_xor_sync(0xffffffffu, mx0, 1));
        mx0 = fmaxf(mx0, __shfl_xor_sync(0xffffffffu, mx0, 2));
        mx1 = fmaxf(mx1, __shfl_xor_sync(0xffffffffu, mx1, 1));
        mx1 = fmaxf(mx1, __shfl_xor_sync(0xffffffffu, mx1, 2));
        const float mn0 = fmaxf(m0, mx0), mn1 = fmaxf(m1, mx1);
        const float cr0 = ex2f(m0 - mn0), cr1 = ex2f(m1 - mn1);
        float sum0 = 0.f, sum1 = 0.f;
        const int pr0 = w * 16 + gid;
        #pragma unroll
        for (int nt = 0; nt < 8; nt++) {
            float p0 = ex2f(s[nt][0] - mn0); sum0 += p0;
            float p1 = ex2f(s[nt][1] - mn0); sum0 += p1;
            float p2 = ex2f(s[nt][2] - mn1); sum1 += p2;
            float p3 = ex2f(s[nt][3] - mn1); sum1 += p3;
            __half2 h01 = __floats2half2_rn(p0, p1);
            __half2 h23 = __floats2half2_rn(p2, p3);
            *(uint32_t*)&Pv[pr0 * PS_STRIDE + nt * 8 + 2 * tig]       = *(uint32_t*)&h01;
            *(uint32_t*)&Pv[(pr0 + 8) * PS_STRIDE + nt * 8 + 2 * tig] = *(uint32_t*)&h23;
        }
        sum0 += __shfl_xor_sync(0xffffffffu, sum0, 1);
        sum0 += __shfl_xor_sync(0xffffffffu, sum0, 2);
        sum1 += __shfl_xor_sync(0xffffffffu, sum1, 1);
        sum1 += __shfl_xor_sync(0xffffffffu, sum1, 2);
        l0 = l0 * cr0 + sum0;  m0 = mn0;
        l1 = l1 * cr1 + sum1;  m1 = mn1;
        if (tig == 0) {
            crow[w * 16 + gid]     = cr0;
            crow[w * 16 + gid + 8] = cr1;
        }
        __syncthreads();

        float cf[4][2];
        #pragma unroll
        for (int mt = 0; mt < 4; mt++) {
            cf[mt][0] = crow[rg * 64 + mt * 16 + gid];
            cf[mt][1] = crow[rg * 64 + mt * 16 + gid + 8];
        }
        #pragma unroll
        for (int mt = 0; mt < 4; mt++)
            #pragma unroll
            for (int nt = 0; nt < 8; nt++) {
                o[mt][nt][0] *= cf[mt][0]; o[mt][nt][1] *= cf[mt][0];
                o[mt][nt][2] *= cf[mt][1]; o[mt][nt][3] *= cf[mt][1];
            }

        #pragma unroll
        for (int kk = 0; kk < 4; kk++) {
            uint32_t a[4][4];
            #pragma unroll
            for (int mt = 0; mt < 4; mt++) {
                const __half* pp = &Pv[(rg * 64 + mt * 16 + gid) * PS_STRIDE + kk * 16 + 2 * tig];
                a[mt][0] = *(const uint32_t*)pp;
                a[mt][1] = *(const uint32_t*)(pp + 8 * PS_STRIDE);
                a[mt][2] = *(const uint32_t*)(pp + 8);
                a[mt][3] = *(const uint32_t*)(pp + 8 * PS_STRIDE + 8);
            }
            #pragma unroll
            for (int nt = 0; nt < 8; nt++) {
                const __half* vp = &Vs[(cg * 64 + nt * 8 + gid) * VS_STRIDE + kk * 16 + 2 * tig];
                uint32_t b0 = *(const uint32_t*)vp;
                uint32_t b1 = *(const uint32_t*)(vp + 8);
                #pragma unroll
                for (int mt = 0; mt < 4; mt++)
                    mma16(o[mt][nt], a[mt], b0, b1);
            }
        }
        __syncthreads();
    }

    if (tig == 0) {
        lrow[w * 16 + gid]     = l0;
        lrow[w * 16 + gid + 8] = l1;
    }
    __syncthreads();

    float inv[4][2];
    #pragma unroll
    for (int mt = 0; mt < 4; mt++) {
        inv[mt][0] = 1.f / lrow[rg * 64 + mt * 16 + gid];
        inv[mt][1] = 1.f / lrow[rg * 64 + mt * 16 + gid + 8];
    }

    #pragma unroll
    for (int mt = 0; mt < 4; mt++) {
        const int i_a = i0g + rg * 64 + mt * 16 + gid;
        const int i_b = i_a + 8;
        #pragma unroll
        for (int nt = 0; nt < 8; nt++) {
            const int c0 = cg * 64 + nt * 8 + 2 * tig;
            out[((size_t)n * C + c0) * HW + i_a]     = o[mt][nt][0] * inv[mt][0];
            out[((size_t)n * C + c0 + 1) * HW + i_a] = o[mt][nt][1] * inv[mt][0];
            out[((size_t)n * C + c0) * HW + i_b]     = o[mt][nt][2] * inv[mt][1];
            out[((size_t)n * C + c0 + 1) * HW + i_b] = o[mt][nt][3] * inv[mt][1];
        }
    }
}

extern "C" void kernel_launch(void* const* d_in, const int* in_sizes, int n_in,
                              void* d_out, int out_size)
{
    const float* x  = (const float*)d_in[0];
    const float* Wq = (const float*)d_in[1];
    const float* bq = (const float*)d_in[2];
    const float* Wk = (const float*)d_in[3];
    const float* bk = (const float*)d_in[4];
    const float* Wv = (const float*)d_in[5];
    const float* bv = (const float*)d_in[6];
    float* out = (float*)d_out;

    convert_kernel<<<4096 + 80, 256>>>(x, Wq, Wk, Wv);

    cudaFuncSetAttribute(proj_mma, cudaFuncAttributeMaxDynamicSharedMemorySize, PROJ_SMEM);
    dim3 pg(5, 32, NB);
    proj_mma<<<pg, 256, PROJ_SMEM>>>(bq, bk, bv);

    cudaFuncSetAttribute(flash_fp16, cudaFuncAttributeMaxDynamicSharedMemorySize, SM_BYTES);
    dim3 fg(HW / BM, NB);
    flash_fp16<<<fg, 256, SM_BYTES>>>(out);
}